// round 15
// baseline (speedup 1.0000x reference)
#include <cuda_runtime.h>
#include <cuda_fp16.h>
#include <math.h>

#define NB_RAYS 2048
#define RESV    192
#define RADF    1.3f
#define STEPF   0.0352f

// ---- fp16 transposed weight tiles W^T[N][K_pad] ----
#define WS_L0 40
#define WS_L1 136
#define WS_L2 136
#define WS_C0 40
#define WS_C1 72
#define B_L0 0
#define B_L1 10240
#define B_L2 45056
#define B_C0 49408
#define B_C1 54528
#define WT_BYTES 63744

#define SM_CW2 63744          // 192 floats fp32
#define SM_X   64512          // X: 128 rows x 136 halfs (272 B) = 34816 B
#define SM_RED 99328          // wtot(16B) + part(64B)
#define SMEM_TOTAL 99456

#define XS 136                // X stride in halfs (272 B per row)

#define GRID3 (192*192*192)

__device__ __align__(16) unsigned char g_wt[WT_BYTES];
__device__ __align__(16) __half g_grid[(size_t)GRID3 * 4];   // dense rank-8 grid, fp16, 56.6MB
__device__ __align__(16) __half g_fgh[32*32*32*32];          // fp16 feature grid, 2MB

typedef unsigned long long u64;

__device__ __forceinline__ float relu_(float v) { return v > 0.f ? v : 0.f; }

__device__ __forceinline__ unsigned smem_u32(const void* p) {
    unsigned a;
    asm("{ .reg .u64 t; cvta.to.shared.u64 t, %1; cvt.u32.u64 %0, t; }" : "=r"(a) : "l"(p));
    return a;
}
__device__ __forceinline__ unsigned h2u_(float a, float b) {
    __half2 h = __floats2half2_rn(a, b);
    return *reinterpret_cast<unsigned*>(&h);
}
__device__ __forceinline__ void ldsm4_(unsigned* r, unsigned a) {
    asm volatile("ldmatrix.sync.aligned.m8n8.x4.shared.b16 {%0,%1,%2,%3}, [%4];"
        : "=r"(r[0]), "=r"(r[1]), "=r"(r[2]), "=r"(r[3]) : "r"(a));
}
__device__ __forceinline__ void mma_(float& c0, float& c1, float& c2, float& c3,
    unsigned a0, unsigned a1, unsigned a2, unsigned a3, unsigned b0, unsigned b1) {
    asm volatile("mma.sync.aligned.m16n8k16.row.col.f32.f16.f16.f32 "
        "{%0,%1,%2,%3}, {%4,%5,%6,%7}, {%8,%9}, {%0,%1,%2,%3};"
        : "+f"(c0), "+f"(c1), "+f"(c2), "+f"(c3)
        : "r"(a0), "r"(a1), "r"(a2), "r"(a3), "r"(b0), "r"(b1));
}
__device__ __forceinline__ void sts32_(unsigned a, unsigned v) {
    asm volatile("st.shared.b32 [%0], %1;" :: "r"(a), "r"(v) : "memory");
}

// ---- one MLP layer on tensor cores; warp-local; in-place in X ----
// B loaded via ldmatrix.x4: one instruction covers (nt, nt+1) x k16.
template<int NT, int KT, int WS, bool FP32OUT>
__device__ __forceinline__ void layer_(unsigned xb, unsigned wb, int m0, int lane) {
    const int gid = lane >> 2, tig = lane & 3;

    unsigned A[2][KT * 4];
    {
        const unsigned koff8 = (unsigned)((lane >> 4) * 8);
#pragma unroll
        for (int mt = 0; mt < 2; mt++) {
            const unsigned abase = xb + (unsigned)(m0 + mt*16 + (lane & 15)) * (XS * 2);
#pragma unroll
            for (int kt = 0; kt < KT; kt++)
                ldsm4_(&A[mt][kt*4], abase + (kt*16 + koff8) * 2);
        }
    }
    __syncwarp();

    const int quad = lane >> 3;           // 0..3
    const int nsel = quad >> 1;           // 0: nt, 1: nt+1
    const int ksel = quad & 1;            // 0: k 0-7, 1: k 8-15

#pragma unroll
    for (int nt = 0; nt < NT; nt += 2) {
        unsigned B[KT * 4];
        {
            const unsigned bbase = wb + (unsigned)((nt + nsel)*8 + (lane & 7)) * (WS * 2);
#pragma unroll
            for (int kt = 0; kt < KT; kt++)
                ldsm4_(&B[kt*4], bbase + (kt*16 + ksel*8) * 2);
        }
#pragma unroll
        for (int np = 0; np < 2; np++) {
#pragma unroll
            for (int mt = 0; mt < 2; mt++) {
                float c0 = 0.f, c1 = 0.f, c2 = 0.f, c3 = 0.f;
#pragma unroll
                for (int kt = 0; kt < KT; kt++)
                    mma_(c0, c1, c2, c3,
                         A[mt][kt*4+0], A[mt][kt*4+1], A[mt][kt*4+2], A[mt][kt*4+3],
                         B[kt*4 + np*2 + 0], B[kt*4 + np*2 + 1]);
                const int row = m0 + mt*16 + gid;
                const int col = (nt + np)*8 + 2*tig;
                if (FP32OUT) {
                    unsigned a0 = xb + (unsigned)row * (XS*2) + (unsigned)col * 4;
                    sts32_(a0,     __float_as_uint(c0));
                    sts32_(a0 + 4, __float_as_uint(c1));
                    unsigned a1 = xb + (unsigned)(row + 8) * (XS*2) + (unsigned)col * 4;
                    sts32_(a1,     __float_as_uint(c2));
                    sts32_(a1 + 4, __float_as_uint(c3));
                } else {
                    sts32_(xb + (unsigned)row       * (XS*2) + (unsigned)col * 2, h2u_(relu_(c0), relu_(c1)));
                    sts32_(xb + (unsigned)(row + 8) * (XS*2) + (unsigned)col * 2, h2u_(relu_(c2), relu_(c3)));
                }
            }
        }
    }
    __syncwarp();
}

// ---- helpers ----
__device__ __forceinline__ void prep_(float c, int size, int& i0, float& w) {
    float idx = (c + 1.f) * 0.5f * (float)(size - 1);
    idx = fminf(fmaxf(idx, 0.f), (float)(size - 1));
    int i = (int)floorf(idx);
    if (i > size - 2) i = size - 2;
    i0 = i; w = idx - (float)i;
}
__device__ __forceinline__ void load24_(float* dst, const float* src) {
    const float4* q = reinterpret_cast<const float4*>(src);
#pragma unroll
    for (int i = 0; i < 6; i++) {
        float4 v = q[i];
        dst[4*i+0] = v.x; dst[4*i+1] = v.y; dst[4*i+2] = v.z; dst[4*i+3] = v.w;
    }
}

// features via dense fp16 grid (8x LDG.64) + fp16 feature grid
__device__ __forceinline__ void features_(float p0, float p1, float p2, float* fv)
{
    const float cx = (p0 * (1.f/RADF) + 1.f) * 96.f * (2.f/192.f) - 1.f;
    const float cy = (p1 * (1.f/RADF) + 1.f) * 96.f * (2.f/192.f) - 1.f;
    const float cz = (p2 * (1.f/RADF) + 1.f) * 96.f * (2.f/192.f) - 1.f;
    int x0, y0, z0; float wx, wy, wz;
    prep_(cx, RESV, x0, wx); prep_(cy, RESV, y0, wy); prep_(cz, RESV, z0, wz);

    float gval[3] = {0.f, 0.f, 0.f};
#pragma unroll
    for (int dz = 0; dz < 2; dz++) {
        const float wzv = dz ? wz : 1.f - wz;
#pragma unroll
        for (int dy = 0; dy < 2; dy++) {
            const float wzy = wzv * (dy ? wy : 1.f - wy);
#pragma unroll
            for (int dx = 0; dx < 2; dx++) {
                const float w = wzy * (dx ? wx : 1.f - wx);
                const uint2 pk = *(const uint2*)(g_grid +
                    ((size_t)((z0+dz)*RESV + (y0+dy))*RESV + (x0+dx)) * 4);
                const float2 f01 = __half22float2(*reinterpret_cast<const __half2*>(&pk.x));
                const float2 f2x = __half22float2(*reinterpret_cast<const __half2*>(&pk.y));
                gval[0] = fmaf(w, f01.x, gval[0]);
                gval[1] = fmaf(w, f01.y, gval[1]);
                gval[2] = fmaf(w, f2x.x, gval[2]);
            }
        }
    }

    int fx0, fy0, fz0; float fwx, fwy, fwz;
    prep_(gval[0], 32, fx0, fwx); prep_(gval[1], 32, fy0, fwy); prep_(gval[2], 32, fz0, fwz);

#pragma unroll
    for (int i = 0; i < 32; i++) fv[i] = 0.f;
#pragma unroll
    for (int dz = 0; dz < 2; dz++) {
        const float wzv = dz ? fwz : 1.f - fwz;
#pragma unroll
        for (int dy = 0; dy < 2; dy++) {
            const float wzy = wzv * (dy ? fwy : 1.f - fwy);
#pragma unroll
            for (int dx = 0; dx < 2; dx++) {
                const float w = wzy * (dx ? fwx : 1.f - fwx);
                const uint4* q = (const uint4*)(g_fgh +
                    (size_t)(((fz0+dz)*32 + (fy0+dy))*32 + (fx0+dx))*32);
#pragma unroll
                for (int i = 0; i < 4; i++) {
                    uint4 v = q[i];
                    const unsigned u[4] = {v.x, v.y, v.z, v.w};
#pragma unroll
                    for (int j = 0; j < 4; j++) {
                        float2 f = __half22float2(*reinterpret_cast<const __half2*>(&u[j]));
                        fv[i*8 + 2*j + 0] = fmaf(w, f.x, fv[i*8 + 2*j + 0]);
                        fv[i*8 + 2*j + 1] = fmaf(w, f.y, fv[i*8 + 2*j + 1]);
                    }
                }
            }
        }
    }
}

// ---- fused prep: weights -> fp16 tiles, Fg -> fp16, dense rank-8 grid ----
// 1152 blocks x 256 thr; 6 z-slices staged per barrier pair (8 barriers/block).
__global__ __launch_bounds__(256)
void grid_prep(const float* __restrict__ Gxy, const float* __restrict__ Gxz,
               const float* __restrict__ Gyz, const float* __restrict__ Fg,
               const float* __restrict__ sW0, const float* __restrict__ sW1,
               const float* __restrict__ sW2, const float* __restrict__ cW0,
               const float* __restrict__ cW1) {
    // --- part A: weight + Fg conversion (grid-strided) ---
    {
        const float* Ws[5] = {sW0, sW1, sW2, cW0, cW1};
        const int Ns[5]  = {128, 128, 16, 64, 64};
        const int Ks[5]  = {32, 128, 128, 31, 64};
        const int WSs[5] = {WS_L0, WS_L1, WS_L2, WS_C0, WS_C1};
        const int Bs[5]  = {B_L0, B_L1, B_L2, B_C0, B_C1};
        const int gtid = blockIdx.x * blockDim.x + threadIdx.x;
        const int gnth = gridDim.x * blockDim.x;
#pragma unroll 1
        for (int l = 0; l < 5; l++) {
            const int N = Ns[l], K = Ks[l], WS = WSs[l];
            const float* W = Ws[l];
            for (int idx = gtid; idx < N * WS; idx += gnth) {
                const int n = idx / WS, k = idx % WS;
                const float v = (k < K) ? W[k * N + n] : 0.f;
                *(__half*)(g_wt + Bs[l] + (size_t)(n * WS + k) * 2) = __float2half_rn(v);
            }
        }
        for (int i = gtid; i < 32*32*32*32; i += gnth)
            g_fgh[i] = __float2half_rn(Fg[i]);
    }

    // --- part B: dense grid(z,y,x)[c] = sum_r Gxy*Gxz*Gyz ---
    __shared__ float s_gxy[6][16*24];
    __shared__ float s_gxz[6][16*24];
    const int t  = threadIdx.x;
    const int ty = t >> 4, tx = t & 15;
    const int tile = blockIdx.x >> 3;          // 0..143
    const int zc   = blockIdx.x & 7;           // 0..7 (24 z each)
    const int y0 = (tile / 12) * 16, x0 = (tile % 12) * 16;
    const int y = y0 + ty, x = x0 + tx;

    float gyz[24];
    load24_(gyz, Gyz + (size_t)(y*RESV + x)*24);

#pragma unroll 1
    for (int it = 0; it < 4; it++) {
        const int zb = zc*24 + it*6;
        __syncthreads();    // previous iteration's reads complete
        // stage 6 z-slices of gxy/gxz rows: 1152 float4 total
#pragma unroll 1
        for (int i = t; i < 1152; i += 256) {
            const int zi = i / 192, r = i % 192;
            const int z = zb + zi;
            if (r < 96)
                ((float4*)s_gxy[zi])[r] =
                    ((const float4*)(Gxy + (size_t)(z*RESV + y0)*24))[r];
            else
                ((float4*)s_gxz[zi])[r-96] =
                    ((const float4*)(Gxz + (size_t)(z*RESV + x0)*24))[r-96];
        }
        __syncthreads();

#pragma unroll 1
        for (int zi = 0; zi < 6; zi++) {
            const int z = zb + zi;
            float a[3];
#pragma unroll
            for (int c = 0; c < 3; c++) {
                float acc = 0.f;
#pragma unroll
                for (int r = 0; r < 8; r++)
                    acc = fmaf(s_gxy[zi][ty*24 + c*8 + r],
                               s_gxz[zi][tx*24 + c*8 + r] * gyz[c*8 + r], acc);
                a[c] = acc;
            }
            __half2 h01 = __floats2half2_rn(a[0], a[1]);
            __half2 h2x = __floats2half2_rn(a[2], 0.f);
            uint2 pk;
            pk.x = *reinterpret_cast<unsigned*>(&h01);
            pk.y = *reinterpret_cast<unsigned*>(&h2x);
            *(uint2*)(g_grid + ((size_t)(z*RESV + y)*RESV + x)*4) = pk;
        }
    }
}

// ---- main kernel: 1 block = 1 ray = 128 samples, 4 warps, warp-skip ----
__global__ __launch_bounds__(128)
void nerf_mma_kernel(
    const float* __restrict__ rays_o, const float* __restrict__ rays_d,
    const float* __restrict__ cW2, float* __restrict__ out)
{
    extern __shared__ unsigned char sm[];
    const unsigned smem_base = smem_u32(sm);
    const int tid  = threadIdx.x;
    const int wid  = tid >> 5;
    const int lane = tid & 31;
    const int m0   = wid * 32;
    const int ray  = blockIdx.x;
    const unsigned xb = smem_base + SM_X;

    // ---- ray/sample setup (sample index = tid) ----
    const float ro0 = rays_o[ray*3+0], ro1 = rays_o[ray*3+1], ro2 = rays_o[ray*3+2];
    const float rd0 = rays_d[ray*3+0], rd1 = rays_d[ray*3+1], rd2 = rays_d[ray*3+2];
    const float dd0 = fabsf(rd0) < 1e-9f ? 1e-9f : rd0;
    const float dd1 = fabsf(rd1) < 1e-9f ? 1e-9f : rd1;
    const float dd2 = fabsf(rd2) < 1e-9f ? 1e-9f : rd2;
    const float t1a = (-RADF - ro0) / dd0, t2a = (RADF - ro0) / dd0;
    const float t1b = (-RADF - ro1) / dd1, t2b = (RADF - ro1) / dd1;
    const float t1c = (-RADF - ro2) / dd2, t2c = (RADF - ro2) / dd2;
    const float tmin = fmaxf(fmaxf(fminf(t1a,t2a), fminf(t1b,t2b)), fminf(t1c,t2c));
    const float tmax = fminf(fminf(fmaxf(t1a,t2a), fmaxf(t1b,t2b)), fmaxf(t1c,t2c));
    const float nearv = fmaxf(tmin, 0.f);
    const float ts0 = nearv + (float)tid * STEPF;
    const float ts1 = nearv + (float)(tid+1) * STEPF;
    const float tmid = 0.5f * (ts0 + ts1);
    const float dist = ts1 - ts0;
    const float p0 = ro0 + tmid*rd0, p1 = ro1 + tmid*rd1, p2 = ro2 + tmid*rd2;
    const bool mask = (fabsf(p0)<=RADF) && (fabsf(p1)<=RADF) && (fabsf(p2)<=RADF)
                      && (tmid<=tmax) && (tmax>tmin);

    const bool warp_active = __any_sync(0xffffffffu, mask);

    // stage weights + cW2
    {
        const float4* s = (const float4*)g_wt;
        float4* d = (float4*)sm;
        for (int i = tid; i < WT_BYTES/16; i += 128) d[i] = s[i];
        float* dc = (float*)(sm + SM_CW2);
        for (int i = tid; i < 192; i += 128) dc[i] = cW2[i];
    }
    __syncthreads();

    float sigma = 0.f, col0 = 0.f, col1 = 0.f, col2 = 0.f;

    if (warp_active) {
        // ---- features -> X row (fp16, cols 0..31) ----
        {
            float fv[32];
            features_(p0, p1, p2, fv);
            const unsigned rbase = xb + (unsigned)tid * (XS*2);
#pragma unroll
            for (int j = 0; j < 16; j++)
                sts32_(rbase + j*4, h2u_(fv[2*j], fv[2*j+1]));
        }
        __syncwarp();

        // ---- sigma MLP on tensor cores (warp-local) ----
        layer_<16, 2, WS_L0, false>(xb, smem_base + B_L0, m0, lane);  // 32 -> 128
        layer_<16, 8, WS_L1, false>(xb, smem_base + B_L1, m0, lane);  // 128 -> 128
        layer_< 2, 8, WS_L2, true >(xb, smem_base + B_L2, m0, lane);  // 128 -> 16 fp32

        // ---- read own o16, build color input ci[32] ----
        {
            const unsigned rbase = xb + (unsigned)tid * (XS*2);
            float o16[16];
#pragma unroll
            for (int j = 0; j < 4; j++) {
                float4 v = *(const float4*)(sm + SM_X + (size_t)tid*(XS*2) + j*16);
                o16[4*j+0] = v.x; o16[4*j+1] = v.y; o16[4*j+2] = v.z; o16[4*j+3] = v.w;
            }
            sigma = relu_(o16[0]);

            const float inv = rsqrtf(rd0*rd0 + rd1*rd1 + rd2*rd2);
            const float x = rd0*inv, y = rd1*inv, z = rd2*inv;
            const float x2 = x*x, y2 = y*y, z2 = z*z;
            float ci[32];
            ci[0]  = 0.28209479177387814f;
            ci[1]  = -0.48860251190291987f * y;
            ci[2]  =  0.48860251190291987f * z;
            ci[3]  = -0.48860251190291987f * x;
            ci[4]  =  1.0925484305920792f * x * y;
            ci[5]  = -1.0925484305920792f * y * z;
            ci[6]  =  0.94617469575756f * z2 - 0.31539156525252f;
            ci[7]  = -1.0925484305920792f * x * z;
            ci[8]  =  0.5462742152960396f * (x2 - y2);
            ci[9]  =  0.5900435899266435f * y * (-3.0f*x2 + y2);
            ci[10] =  2.890611442640554f * x * y * z;
            ci[11] =  0.4570457994644657f * y * (1.0f - 5.0f*z2);
            ci[12] =  0.3731763325901154f * z * (5.0f*z2 - 3.0f);
            ci[13] =  0.4570457994644657f * x * (1.0f - 5.0f*z2);
            ci[14] =  1.445305721320277f * z * (x2 - y2);
            ci[15] =  0.5900435899266435f * x * (-x2 + 3.0f*y2);
#pragma unroll
            for (int k = 0; k < 15; k++) ci[16+k] = o16[1+k];
            ci[31] = 0.f;
            __syncwarp();
#pragma unroll
            for (int j = 0; j < 16; j++)
                sts32_(rbase + j*4, h2u_(ci[2*j], ci[2*j+1]));
        }
        __syncwarp();

        // ---- color MLP ----
        layer_<8, 2, WS_C0, false>(xb, smem_base + B_C0, m0, lane);  // 32 -> 64
        layer_<8, 4, WS_C1, false>(xb, smem_base + B_C1, m0, lane);  // 64 -> 64

        // ---- cW2: 64 -> 3 scalar ----
        {
            const float* cw2s = (const float*)(sm + SM_CW2);
            const __half2* xr = (const __half2*)(sm + SM_X + (size_t)tid*(XS*2));
#pragma unroll
            for (int j = 0; j < 32; j++) {
                float2 h = __half22float2(xr[j]);
                col0 = fmaf(h.x, cw2s[(2*j)*3+0], col0);
                col1 = fmaf(h.x, cw2s[(2*j)*3+1], col1);
                col2 = fmaf(h.x, cw2s[(2*j)*3+2], col2);
                col0 = fmaf(h.y, cw2s[(2*j+1)*3+0], col0);
                col1 = fmaf(h.y, cw2s[(2*j+1)*3+1], col1);
                col2 = fmaf(h.y, cw2s[(2*j+1)*3+2], col2);
            }
        }

        if (!mask) { sigma = 0.f; col0 = col1 = col2 = 0.f; }
    }

    // ---- volume rendering ----
    float* s_wtot = (float*)(sm + SM_RED);
    float* s_part = (float*)(sm + SM_RED + 16);

    const float e = expf(-sigma * dist);
    const float a = e + 1e-10f;
    const float alpha = 1.f - e;

    float incl = a;
#pragma unroll
    for (int off = 1; off < 32; off <<= 1) {
        float v = __shfl_up_sync(0xffffffffu, incl, off);
        if (lane >= off) incl *= v;
    }
    float excl = __shfl_up_sync(0xffffffffu, incl, 1);
    if (lane == 0) excl = 1.f;
    if (lane == 31) s_wtot[wid] = incl;
    __syncthreads();

    float offp = 1.f;
    for (int w2 = 0; w2 < wid; w2++) offp *= s_wtot[w2];
    const float T = offp * excl;
    const float wgt = alpha * T;

    const float r0 = 1.f / (1.f + expf(-col0));
    const float r1 = 1.f / (1.f + expf(-col1));
    const float r2 = 1.f / (1.f + expf(-col2));

    float v0 = wgt, v1 = wgt*r0, v2 = wgt*r1, v3 = wgt*r2;
#pragma unroll
    for (int off = 16; off >= 1; off >>= 1) {
        v0 += __shfl_xor_sync(0xffffffffu, v0, off);
        v1 += __shfl_xor_sync(0xffffffffu, v1, off);
        v2 += __shfl_xor_sync(0xffffffffu, v2, off);
        v3 += __shfl_xor_sync(0xffffffffu, v3, off);
    }
    if (lane == 0) {
        s_part[wid*4+0] = v0; s_part[wid*4+1] = v1;
        s_part[wid*4+2] = v2; s_part[wid*4+3] = v3;
    }
    __syncthreads();

    if (tid < 3) {
        float ws = 0.f, cs = 0.f;
#pragma unroll
        for (int w2 = 0; w2 < 4; w2++) {
            ws += s_part[w2*4+0];
            cs += s_part[w2*4+1+tid];
        }
        out[ray*3 + tid] = cs + (1.f - ws);
    }
}

extern "C" void kernel_launch(void* const* d_in, const int* in_sizes, int n_in,
                              void* d_out, int out_size) {
    const float* rays_o = (const float*)d_in[0];
    const float* rays_d = (const float*)d_in[1];
    const float* Gxy    = (const float*)d_in[2];
    const float* Gxz    = (const float*)d_in[3];
    const float* Gyz    = (const float*)d_in[4];
    const float* Fg     = (const float*)d_in[5];
    const float* sW0    = (const float*)d_in[6];
    const float* sW1    = (const float*)d_in[7];
    const float* sW2    = (const float*)d_in[8];
    const float* cW0    = (const float*)d_in[9];
    const float* cW1    = (const float*)d_in[10];
    const float* cW2    = (const float*)d_in[11];
    float* out = (float*)d_out;

    grid_prep<<<144*8, 256>>>(Gxy, Gxz, Gyz, Fg, sW0, sW1, sW2, cW0, cW1);

    cudaFuncSetAttribute(nerf_mma_kernel,
                         cudaFuncAttributeMaxDynamicSharedMemorySize, SMEM_TOTAL);
    nerf_mma_kernel<<<NB_RAYS, 128, SMEM_TOTAL>>>(rays_o, rays_d, cW2, out);
}

// round 16
// speedup vs baseline: 1.2108x; 1.2108x over previous
#include <cuda_runtime.h>
#include <cuda_fp16.h>
#include <math.h>

#define NB_RAYS 2048
#define RESV    192
#define RADF    1.3f
#define STEPF   0.0352f

// ---- fp16 transposed weight tiles W^T[N][K_pad] ----
#define WS_L0 40
#define WS_L1 136
#define WS_L2 136
#define WS_C0 40
#define WS_C1 72
#define B_L0 0
#define B_L1 10240
#define B_L2 45056
#define B_C0 49408
#define B_C1 54528
#define WT_BYTES 63744

#define SM_CW2 63744          // 192 floats fp32
#define SM_X   64512          // X: 128 rows x 136 halfs (272 B) = 34816 B
#define SM_RED 99328          // wtot(16B) + part(64B)
#define SMEM_TOTAL 99456

#define XS 136                // X stride in halfs (272 B per row)

#define GRID3 (192*192*192)

__device__ __align__(16) unsigned char g_wt[WT_BYTES];
__device__ __align__(16) __half g_grid[(size_t)GRID3 * 4];   // dense rank-8 grid, fp16, 56.6MB
__device__ __align__(16) __half g_fgh[32*32*32*32];          // fp16 feature grid, 2MB

typedef unsigned long long u64;

__device__ __forceinline__ float relu_(float v) { return v > 0.f ? v : 0.f; }

__device__ __forceinline__ unsigned smem_u32(const void* p) {
    unsigned a;
    asm("{ .reg .u64 t; cvta.to.shared.u64 t, %1; cvt.u32.u64 %0, t; }" : "=r"(a) : "l"(p));
    return a;
}
__device__ __forceinline__ unsigned h2u_(float a, float b) {
    __half2 h = __floats2half2_rn(a, b);
    return *reinterpret_cast<unsigned*>(&h);
}
__device__ __forceinline__ void ldsm4_(unsigned* r, unsigned a) {
    asm volatile("ldmatrix.sync.aligned.m8n8.x4.shared.b16 {%0,%1,%2,%3}, [%4];"
        : "=r"(r[0]), "=r"(r[1]), "=r"(r[2]), "=r"(r[3]) : "r"(a));
}
__device__ __forceinline__ void mma_(float& c0, float& c1, float& c2, float& c3,
    unsigned a0, unsigned a1, unsigned a2, unsigned a3, unsigned b0, unsigned b1) {
    asm volatile("mma.sync.aligned.m16n8k16.row.col.f32.f16.f16.f32 "
        "{%0,%1,%2,%3}, {%4,%5,%6,%7}, {%8,%9}, {%0,%1,%2,%3};"
        : "+f"(c0), "+f"(c1), "+f"(c2), "+f"(c3)
        : "r"(a0), "r"(a1), "r"(a2), "r"(a3), "r"(b0), "r"(b1));
}
__device__ __forceinline__ void sts32_(unsigned a, unsigned v) {
    asm volatile("st.shared.b32 [%0], %1;" :: "r"(a), "r"(v) : "memory");
}

// ---- one MLP layer on tensor cores; warp-local; in-place in X ----
// B loaded via ldmatrix.x4: one instruction covers (nt, nt+1) x k16.
template<int NT, int KT, int WS, bool FP32OUT>
__device__ __forceinline__ void layer_(unsigned xb, unsigned wb, int m0, int lane) {
    const int gid = lane >> 2, tig = lane & 3;

    unsigned A[2][KT * 4];
    {
        const unsigned koff8 = (unsigned)((lane >> 4) * 8);
#pragma unroll
        for (int mt = 0; mt < 2; mt++) {
            const unsigned abase = xb + (unsigned)(m0 + mt*16 + (lane & 15)) * (XS * 2);
#pragma unroll
            for (int kt = 0; kt < KT; kt++)
                ldsm4_(&A[mt][kt*4], abase + (kt*16 + koff8) * 2);
        }
    }
    __syncwarp();

    const int quad = lane >> 3;           // 0..3
    const int nsel = quad >> 1;           // 0: nt, 1: nt+1
    const int ksel = quad & 1;            // 0: k 0-7, 1: k 8-15

#pragma unroll
    for (int nt = 0; nt < NT; nt += 2) {
        unsigned B[KT * 4];
        {
            const unsigned bbase = wb + (unsigned)((nt + nsel)*8 + (lane & 7)) * (WS * 2);
#pragma unroll
            for (int kt = 0; kt < KT; kt++)
                ldsm4_(&B[kt*4], bbase + (kt*16 + ksel*8) * 2);
        }
#pragma unroll
        for (int np = 0; np < 2; np++) {
#pragma unroll
            for (int mt = 0; mt < 2; mt++) {
                float c0 = 0.f, c1 = 0.f, c2 = 0.f, c3 = 0.f;
#pragma unroll
                for (int kt = 0; kt < KT; kt++)
                    mma_(c0, c1, c2, c3,
                         A[mt][kt*4+0], A[mt][kt*4+1], A[mt][kt*4+2], A[mt][kt*4+3],
                         B[kt*4 + np*2 + 0], B[kt*4 + np*2 + 1]);
                const int row = m0 + mt*16 + gid;
                const int col = (nt + np)*8 + 2*tig;
                if (FP32OUT) {
                    unsigned a0 = xb + (unsigned)row * (XS*2) + (unsigned)col * 4;
                    sts32_(a0,     __float_as_uint(c0));
                    sts32_(a0 + 4, __float_as_uint(c1));
                    unsigned a1 = xb + (unsigned)(row + 8) * (XS*2) + (unsigned)col * 4;
                    sts32_(a1,     __float_as_uint(c2));
                    sts32_(a1 + 4, __float_as_uint(c3));
                } else {
                    sts32_(xb + (unsigned)row       * (XS*2) + (unsigned)col * 2, h2u_(relu_(c0), relu_(c1)));
                    sts32_(xb + (unsigned)(row + 8) * (XS*2) + (unsigned)col * 2, h2u_(relu_(c2), relu_(c3)));
                }
            }
        }
    }
    __syncwarp();
}

// ---- helpers ----
__device__ __forceinline__ void prep_(float c, int size, int& i0, float& w) {
    float idx = (c + 1.f) * 0.5f * (float)(size - 1);
    idx = fminf(fmaxf(idx, 0.f), (float)(size - 1));
    int i = (int)floorf(idx);
    if (i > size - 2) i = size - 2;
    i0 = i; w = idx - (float)i;
}
__device__ __forceinline__ void load24_(float* dst, const float* src) {
    const float4* q = reinterpret_cast<const float4*>(src);
#pragma unroll
    for (int i = 0; i < 6; i++) {
        float4 v = q[i];
        dst[4*i+0] = v.x; dst[4*i+1] = v.y; dst[4*i+2] = v.z; dst[4*i+3] = v.w;
    }
}
__device__ __forceinline__ void lds24_(float* dst, const float* s) {
#pragma unroll
    for (int i = 0; i < 6; i++) {
        float4 v = ((const float4*)s)[i];
        dst[4*i+0] = v.x; dst[4*i+1] = v.y; dst[4*i+2] = v.z; dst[4*i+3] = v.w;
    }
}

// features via dense fp16 grid (8x LDG.64) + fp16 feature grid
__device__ __forceinline__ void features_(float p0, float p1, float p2, float* fv)
{
    const float cx = (p0 * (1.f/RADF) + 1.f) * 96.f * (2.f/192.f) - 1.f;
    const float cy = (p1 * (1.f/RADF) + 1.f) * 96.f * (2.f/192.f) - 1.f;
    const float cz = (p2 * (1.f/RADF) + 1.f) * 96.f * (2.f/192.f) - 1.f;
    int x0, y0, z0; float wx, wy, wz;
    prep_(cx, RESV, x0, wx); prep_(cy, RESV, y0, wy); prep_(cz, RESV, z0, wz);

    float gval[3] = {0.f, 0.f, 0.f};
#pragma unroll
    for (int dz = 0; dz < 2; dz++) {
        const float wzv = dz ? wz : 1.f - wz;
#pragma unroll
        for (int dy = 0; dy < 2; dy++) {
            const float wzy = wzv * (dy ? wy : 1.f - wy);
#pragma unroll
            for (int dx = 0; dx < 2; dx++) {
                const float w = wzy * (dx ? wx : 1.f - wx);
                const uint2 pk = *(const uint2*)(g_grid +
                    ((size_t)((z0+dz)*RESV + (y0+dy))*RESV + (x0+dx)) * 4);
                const float2 f01 = __half22float2(*reinterpret_cast<const __half2*>(&pk.x));
                const float2 f2x = __half22float2(*reinterpret_cast<const __half2*>(&pk.y));
                gval[0] = fmaf(w, f01.x, gval[0]);
                gval[1] = fmaf(w, f01.y, gval[1]);
                gval[2] = fmaf(w, f2x.x, gval[2]);
            }
        }
    }

    int fx0, fy0, fz0; float fwx, fwy, fwz;
    prep_(gval[0], 32, fx0, fwx); prep_(gval[1], 32, fy0, fwy); prep_(gval[2], 32, fz0, fwz);

#pragma unroll
    for (int i = 0; i < 32; i++) fv[i] = 0.f;
#pragma unroll
    for (int dz = 0; dz < 2; dz++) {
        const float wzv = dz ? fwz : 1.f - fwz;
#pragma unroll
        for (int dy = 0; dy < 2; dy++) {
            const float wzy = wzv * (dy ? fwy : 1.f - fwy);
#pragma unroll
            for (int dx = 0; dx < 2; dx++) {
                const float w = wzy * (dx ? fwx : 1.f - fwx);
                const uint4* q = (const uint4*)(g_fgh +
                    (size_t)(((fz0+dz)*32 + (fy0+dy))*32 + (fx0+dx))*32);
#pragma unroll
                for (int i = 0; i < 4; i++) {
                    uint4 v = q[i];
                    const unsigned u[4] = {v.x, v.y, v.z, v.w};
#pragma unroll
                    for (int j = 0; j < 4; j++) {
                        float2 f = __half22float2(*reinterpret_cast<const __half2*>(&u[j]));
                        fv[i*8 + 2*j + 0] = fmaf(w, f.x, fv[i*8 + 2*j + 0]);
                        fv[i*8 + 2*j + 1] = fmaf(w, f.y, fv[i*8 + 2*j + 1]);
                    }
                }
            }
        }
    }
}

// ---- fused prep: weights -> fp16 tiles, Fg -> fp16, dense rank-8 grid ----
// R14 structure (576 blocks x 48 z), but smem row stride padded 24 -> 28
// floats: LDS.128 at stride 112B is bank-conflict-free for 16 lanes.
#define GP_S 28
__global__ __launch_bounds__(256)
void grid_prep(const float* __restrict__ Gxy, const float* __restrict__ Gxz,
               const float* __restrict__ Gyz, const float* __restrict__ Fg,
               const float* __restrict__ sW0, const float* __restrict__ sW1,
               const float* __restrict__ sW2, const float* __restrict__ cW0,
               const float* __restrict__ cW1) {
    // --- part A: weight + Fg conversion (grid-strided) ---
    {
        const float* Ws[5] = {sW0, sW1, sW2, cW0, cW1};
        const int Ns[5]  = {128, 128, 16, 64, 64};
        const int Ks[5]  = {32, 128, 128, 31, 64};
        const int WSs[5] = {WS_L0, WS_L1, WS_L2, WS_C0, WS_C1};
        const int Bs[5]  = {B_L0, B_L1, B_L2, B_C0, B_C1};
        const int gtid = blockIdx.x * blockDim.x + threadIdx.x;
        const int gnth = gridDim.x * blockDim.x;
#pragma unroll 1
        for (int l = 0; l < 5; l++) {
            const int N = Ns[l], K = Ks[l], WS = WSs[l];
            const float* W = Ws[l];
            for (int idx = gtid; idx < N * WS; idx += gnth) {
                const int n = idx / WS, k = idx % WS;
                const float v = (k < K) ? W[k * N + n] : 0.f;
                *(__half*)(g_wt + Bs[l] + (size_t)(n * WS + k) * 2) = __float2half_rn(v);
            }
        }
        for (int i = gtid; i < 32*32*32*32; i += gnth)
            g_fgh[i] = __float2half_rn(Fg[i]);
    }

    // --- part B: dense grid(z,y,x)[c] = sum_r Gxy*Gxz*Gyz ---
    __shared__ float s_gxy[16*GP_S];
    __shared__ float s_gxz[16*GP_S];
    const int t  = threadIdx.x;
    const int ty = t >> 4, tx = t & 15;
    const int tile = blockIdx.x >> 2;
    const int zc   = blockIdx.x & 3;
    const int y0 = (tile / 12) * 16, x0 = (tile % 12) * 16;
    const int y = y0 + ty, x = x0 + tx;

    float gyz[24];
    load24_(gyz, Gyz + (size_t)(y*RESV + x)*24);

    const int zs = zc * 48;
#pragma unroll 1
    for (int z = zs; z < zs + 48; z++) {
        __syncthreads();    // previous iteration's reads complete
        // stage 16 rows x 24 floats into stride-28 rows (float4 granules)
        if (t < 96) {
            const int j = t / 6, q = t % 6;
            ((float4*)(s_gxy + j*GP_S))[q] =
                ((const float4*)(Gxy + (size_t)(z*RESV + y0 + j)*24))[q];
        } else if (t < 192) {
            const int u = t - 96, j = u / 6, q = u % 6;
            ((float4*)(s_gxz + j*GP_S))[q] =
                ((const float4*)(Gxz + (size_t)(z*RESV + x0 + j)*24))[q];
        }
        __syncthreads();

        float xy[24], xz[24];
        lds24_(xy, s_gxy + ty*GP_S);
        lds24_(xz, s_gxz + tx*GP_S);

        float a[3];
#pragma unroll
        for (int c = 0; c < 3; c++) {
            float acc = 0.f;
#pragma unroll
            for (int r = 0; r < 8; r++)
                acc = fmaf(xy[c*8+r], xz[c*8+r] * gyz[c*8+r], acc);
            a[c] = acc;
        }
        __half2 h01 = __floats2half2_rn(a[0], a[1]);
        __half2 h2x = __floats2half2_rn(a[2], 0.f);
        uint2 pk;
        pk.x = *reinterpret_cast<unsigned*>(&h01);
        pk.y = *reinterpret_cast<unsigned*>(&h2x);
        *(uint2*)(g_grid + ((size_t)(z*RESV + y)*RESV + x)*4) = pk;
    }
}

// ---- main kernel: 1 block = 1 ray = 128 samples, 4 warps, warp-skip ----
__global__ __launch_bounds__(128)
void nerf_mma_kernel(
    const float* __restrict__ rays_o, const float* __restrict__ rays_d,
    const float* __restrict__ cW2, float* __restrict__ out)
{
    extern __shared__ unsigned char sm[];
    const unsigned smem_base = smem_u32(sm);
    const int tid  = threadIdx.x;
    const int wid  = tid >> 5;
    const int lane = tid & 31;
    const int m0   = wid * 32;
    const int ray  = blockIdx.x;
    const unsigned xb = smem_base + SM_X;

    // ---- ray/sample setup (sample index = tid) ----
    const float ro0 = rays_o[ray*3+0], ro1 = rays_o[ray*3+1], ro2 = rays_o[ray*3+2];
    const float rd0 = rays_d[ray*3+0], rd1 = rays_d[ray*3+1], rd2 = rays_d[ray*3+2];
    const float dd0 = fabsf(rd0) < 1e-9f ? 1e-9f : rd0;
    const float dd1 = fabsf(rd1) < 1e-9f ? 1e-9f : rd1;
    const float dd2 = fabsf(rd2) < 1e-9f ? 1e-9f : rd2;
    const float t1a = (-RADF - ro0) / dd0, t2a = (RADF - ro0) / dd0;
    const float t1b = (-RADF - ro1) / dd1, t2b = (RADF - ro1) / dd1;
    const float t1c = (-RADF - ro2) / dd2, t2c = (RADF - ro2) / dd2;
    const float tmin = fmaxf(fmaxf(fminf(t1a,t2a), fminf(t1b,t2b)), fminf(t1c,t2c));
    const float tmax = fminf(fminf(fmaxf(t1a,t2a), fmaxf(t1b,t2b)), fmaxf(t1c,t2c));
    const float nearv = fmaxf(tmin, 0.f);
    const float ts0 = nearv + (float)tid * STEPF;
    const float ts1 = nearv + (float)(tid+1) * STEPF;
    const float tmid = 0.5f * (ts0 + ts1);
    const float dist = ts1 - ts0;
    const float p0 = ro0 + tmid*rd0, p1 = ro1 + tmid*rd1, p2 = ro2 + tmid*rd2;
    const bool mask = (fabsf(p0)<=RADF) && (fabsf(p1)<=RADF) && (fabsf(p2)<=RADF)
                      && (tmid<=tmax) && (tmax>tmin);

    const bool warp_active = __any_sync(0xffffffffu, mask);

    // stage weights + cW2
    {
        const float4* s = (const float4*)g_wt;
        float4* d = (float4*)sm;
        for (int i = tid; i < WT_BYTES/16; i += 128) d[i] = s[i];
        float* dc = (float*)(sm + SM_CW2);
        for (int i = tid; i < 192; i += 128) dc[i] = cW2[i];
    }
    __syncthreads();

    float sigma = 0.f, col0 = 0.f, col1 = 0.f, col2 = 0.f;

    if (warp_active) {
        // ---- features -> X row (fp16, cols 0..31) ----
        {
            float fv[32];
            features_(p0, p1, p2, fv);
            const unsigned rbase = xb + (unsigned)tid * (XS*2);
#pragma unroll
            for (int j = 0; j < 16; j++)
                sts32_(rbase + j*4, h2u_(fv[2*j], fv[2*j+1]));
        }
        __syncwarp();

        // ---- sigma MLP on tensor cores (warp-local) ----
        layer_<16, 2, WS_L0, false>(xb, smem_base + B_L0, m0, lane);  // 32 -> 128
        layer_<16, 8, WS_L1, false>(xb, smem_base + B_L1, m0, lane);  // 128 -> 128
        layer_< 2, 8, WS_L2, true >(xb, smem_base + B_L2, m0, lane);  // 128 -> 16 fp32

        // ---- read own o16, build color input ci[32] ----
        {
            const unsigned rbase = xb + (unsigned)tid * (XS*2);
            float o16[16];
#pragma unroll
            for (int j = 0; j < 4; j++) {
                float4 v = *(const float4*)(sm + SM_X + (size_t)tid*(XS*2) + j*16);
                o16[4*j+0] = v.x; o16[4*j+1] = v.y; o16[4*j+2] = v.z; o16[4*j+3] = v.w;
            }
            sigma = relu_(o16[0]);

            const float inv = rsqrtf(rd0*rd0 + rd1*rd1 + rd2*rd2);
            const float x = rd0*inv, y = rd1*inv, z = rd2*inv;
            const float x2 = x*x, y2 = y*y, z2 = z*z;
            float ci[32];
            ci[0]  = 0.28209479177387814f;
            ci[1]  = -0.48860251190291987f * y;
            ci[2]  =  0.48860251190291987f * z;
            ci[3]  = -0.48860251190291987f * x;
            ci[4]  =  1.0925484305920792f * x * y;
            ci[5]  = -1.0925484305920792f * y * z;
            ci[6]  =  0.94617469575756f * z2 - 0.31539156525252f;
            ci[7]  = -1.0925484305920792f * x * z;
            ci[8]  =  0.5462742152960396f * (x2 - y2);
            ci[9]  =  0.5900435899266435f * y * (-3.0f*x2 + y2);
            ci[10] =  2.890611442640554f * x * y * z;
            ci[11] =  0.4570457994644657f * y * (1.0f - 5.0f*z2);
            ci[12] =  0.3731763325901154f * z * (5.0f*z2 - 3.0f);
            ci[13] =  0.4570457994644657f * x * (1.0f - 5.0f*z2);
            ci[14] =  1.445305721320277f * z * (x2 - y2);
            ci[15] =  0.5900435899266435f * x * (-x2 + 3.0f*y2);
#pragma unroll
            for (int k = 0; k < 15; k++) ci[16+k] = o16[1+k];
            ci[31] = 0.f;
            __syncwarp();
#pragma unroll
            for (int j = 0; j < 16; j++)
                sts32_(rbase + j*4, h2u_(ci[2*j], ci[2*j+1]));
        }
        __syncwarp();

        // ---- color MLP ----
        layer_<8, 2, WS_C0, false>(xb, smem_base + B_C0, m0, lane);  // 32 -> 64
        layer_<8, 4, WS_C1, false>(xb, smem_base + B_C1, m0, lane);  // 64 -> 64

        // ---- cW2: 64 -> 3 scalar ----
        {
            const float* cw2s = (const float*)(sm + SM_CW2);
            const __half2* xr = (const __half2*)(sm + SM_X + (size_t)tid*(XS*2));
#pragma unroll
            for (int j = 0; j < 32; j++) {
                float2 h = __half22float2(xr[j]);
                col0 = fmaf(h.x, cw2s[(2*j)*3+0], col0);
                col1 = fmaf(h.x, cw2s[(2*j)*3+1], col1);
                col2 = fmaf(h.x, cw2s[(2*j)*3+2], col2);
                col0 = fmaf(h.y, cw2s[(2*j+1)*3+0], col0);
                col1 = fmaf(h.y, cw2s[(2*j+1)*3+1], col1);
                col2 = fmaf(h.y, cw2s[(2*j+1)*3+2], col2);
            }
        }

        if (!mask) { sigma = 0.f; col0 = col1 = col2 = 0.f; }
    }

    // ---- volume rendering ----
    float* s_wtot = (float*)(sm + SM_RED);
    float* s_part = (float*)(sm + SM_RED + 16);

    const float e = expf(-sigma * dist);
    const float a = e + 1e-10f;
    const float alpha = 1.f - e;

    float incl = a;
#pragma unroll
    for (int off = 1; off < 32; off <<= 1) {
        float v = __shfl_up_sync(0xffffffffu, incl, off);
        if (lane >= off) incl *= v;
    }
    float excl = __shfl_up_sync(0xffffffffu, incl, 1);
    if (lane == 0) excl = 1.f;
    if (lane == 31) s_wtot[wid] = incl;
    __syncthreads();

    float offp = 1.f;
    for (int w2 = 0; w2 < wid; w2++) offp *= s_wtot[w2];
    const float T = offp * excl;
    const float wgt = alpha * T;

    const float r0 = 1.f / (1.f + expf(-col0));
    const float r1 = 1.f / (1.f + expf(-col1));
    const float r2 = 1.f / (1.f + expf(-col2));

    float v0 = wgt, v1 = wgt*r0, v2 = wgt*r1, v3 = wgt*r2;
#pragma unroll
    for (int off = 16; off >= 1; off >>= 1) {
        v0 += __shfl_xor_sync(0xffffffffu, v0, off);
        v1 += __shfl_xor_sync(0xffffffffu, v1, off);
        v2 += __shfl_xor_sync(0xffffffffu, v2, off);
        v3 += __shfl_xor_sync(0xffffffffu, v3, off);
    }
    if (lane == 0) {
        s_part[wid*4+0] = v0; s_part[wid*4+1] = v1;
        s_part[wid*4+2] = v2; s_part[wid*4+3] = v3;
    }
    __syncthreads();

    if (tid < 3) {
        float ws = 0.f, cs = 0.f;
#pragma unroll
        for (int w2 = 0; w2 < 4; w2++) {
            ws += s_part[w2*4+0];
            cs += s_part[w2*4+1+tid];
        }
        out[ray*3 + tid] = cs + (1.f - ws);
    }
}

extern "C" void kernel_launch(void* const* d_in, const int* in_sizes, int n_in,
                              void* d_out, int out_size) {
    const float* rays_o = (const float*)d_in[0];
    const float* rays_d = (const float*)d_in[1];
    const float* Gxy    = (const float*)d_in[2];
    const float* Gxz    = (const float*)d_in[3];
    const float* Gyz    = (const float*)d_in[4];
    const float* Fg     = (const float*)d_in[5];
    const float* sW0    = (const float*)d_in[6];
    const float* sW1    = (const float*)d_in[7];
    const float* sW2    = (const float*)d_in[8];
    const float* cW0    = (const float*)d_in[9];
    const float* cW1    = (const float*)d_in[10];
    const float* cW2    = (const float*)d_in[11];
    float* out = (float*)d_out;

    grid_prep<<<144*4, 256>>>(Gxy, Gxz, Gyz, Fg, sW0, sW1, sW2, cW0, cW1);

    cudaFuncSetAttribute(nerf_mma_kernel,
                         cudaFuncAttributeMaxDynamicSharedMemorySize, SMEM_TOTAL);
    nerf_mma_kernel<<<NB_RAYS, 128, SMEM_TOTAL>>>(rays_o, rays_d, cW2, out);
}